// round 16
// baseline (speedup 1.0000x reference)
#include <cuda_runtime.h>
#include <cuda_bf16.h>
#include <math.h>
#include <stdint.h>

#define NMAX 100000
#define EMAX 2000000
#define DIM 128
#define LN_EPS 1e-5f

// ---------------- helpers ----------------
__device__ __forceinline__ uint32_t smem_to_u32(const void* p) {
    uint32_t a;
    asm("{ .reg .u64 t; cvta.to.shared.u64 t, %1; cvt.u32.u64 %0, t; }" : "=r"(a) : "l"(p));
    return a;
}
// pack two fp32 -> bf16x2 (up -> high 16 bits, low -> low 16 bits)
#define CVT_PACK(res, up, low) \
    asm("cvt.rn.bf16x2.f32 %0, %1, %2;" : "=r"(res) : "f"(up), "f"(low))

__device__ __forceinline__ void ldsm_x4(uint32_t* r, uint32_t addr) {
    asm volatile("ldmatrix.sync.aligned.m8n8.x4.shared.b16 {%0,%1,%2,%3}, [%4];"
                 : "=r"(r[0]), "=r"(r[1]), "=r"(r[2]), "=r"(r[3]) : "r"(addr));
}
__device__ __forceinline__ void mma16816(float* c, const uint32_t* a, const uint32_t* b) {
    asm volatile("mma.sync.aligned.m16n8k16.row.col.f32.bf16.bf16.f32 "
                 "{%0,%1,%2,%3}, {%4,%5,%6,%7}, {%8,%9}, {%0,%1,%2,%3};"
                 : "+f"(c[0]), "+f"(c[1]), "+f"(c[2]), "+f"(c[3])
                 : "r"(a[0]), "r"(a[1]), "r"(a[2]), "r"(a[3]), "r"(b[0]), "r"(b[1]));
}
// exact bf16x2 -> 2x fp32 (bf16 bits are the top 16 of fp32; low half = lower index)
__device__ __forceinline__ float4 unpack_bf4(uint2 u) {
    return make_float4(__uint_as_float(u.x << 16), __uint_as_float(u.x & 0xffff0000u),
                       __uint_as_float(u.y << 16), __uint_as_float(u.y & 0xffff0000u));
}

// ---------------- static scratch ----------------
__device__ int      g_deg [NMAX];
__device__ int      g_off [NMAX + 1];
__device__ int      g_cur [NMAX];
__device__ int      g_srcs[EMAX];
__device__ int      g_bsum[256];
__device__ float    g_dinv[NMAX];
__device__ float    g_Wf  [DIM * 64];
__device__ float    g_bf  [64];
__device__ uint32_t g_zb  [(size_t)NMAX * 64];   // z  (GEMM out, UNSCALED) packed bf16x2
__device__ uint32_t g_hb  [(size_t)NMAX * 64];   // h  (activations) packed bf16x2

// ---------------- CSR build ----------------
__global__ void zero_deg_kernel(int* __restrict__ deg, int n) {
    int i = blockIdx.x * blockDim.x + threadIdx.x;
    if (i < n) deg[i] = 0;
}
__global__ void hist_kernel(const int* __restrict__ dst, int* __restrict__ deg, int E) {
    int t = blockIdx.x * blockDim.x + threadIdx.x;
    int base = t * 4;
    if (base + 3 < E) {
        int4 d = *(const int4*)(dst + base);
        atomicAdd(&deg[d.x], 1);
        atomicAdd(&deg[d.y], 1);
        atomicAdd(&deg[d.z], 1);
        atomicAdd(&deg[d.w], 1);
    } else {
        for (int e = base; e < E; e++) atomicAdd(&deg[dst[e]], 1);
    }
}
__global__ __launch_bounds__(256)
void scan_part_kernel(const int* __restrict__ deg, int* __restrict__ bsum, int n) {
    const int tid = threadIdx.x;
    const int base = blockIdx.x * 1024 + tid * 4;
    int s = 0;
#pragma unroll
    for (int i = 0; i < 4; i++) { int idx = base + i; if (idx < n) s += deg[idx]; }
#pragma unroll
    for (int o = 16; o > 0; o >>= 1) s += __shfl_xor_sync(0xffffffffu, s, o);
    __shared__ int ws[8];
    if ((tid & 31) == 0) ws[tid >> 5] = s;
    __syncthreads();
    if (tid == 0) {
        int t = 0;
#pragma unroll
        for (int i = 0; i < 8; i++) t += ws[i];
        bsum[blockIdx.x] = t;
    }
}
__global__ __launch_bounds__(128)
void scan_block_kernel(int* __restrict__ bsum, int nb) {
    __shared__ int sh[128];
    const int tid = threadIdx.x;
    int v = (tid < nb) ? bsum[tid] : 0;
    sh[tid] = v;
    __syncthreads();
    for (int o = 1; o < 128; o <<= 1) {
        int t = (tid >= o) ? sh[tid - o] : 0;
        __syncthreads();
        sh[tid] += t;
        __syncthreads();
    }
    if (tid < nb) bsum[tid] = sh[tid] - v;
}
__global__ __launch_bounds__(256)
void scan_final_kernel(const int* __restrict__ deg, const int* __restrict__ bsum,
                       int* __restrict__ off, int* __restrict__ cur,
                       float* __restrict__ dinv, int n) {
    const int tid = threadIdx.x;
    const int lane = tid & 31, w = tid >> 5;
    const int base = blockIdx.x * 1024 + tid * 4;
    int d[4]; int s = 0;
#pragma unroll
    for (int i = 0; i < 4; i++) { int idx = base + i; d[i] = (idx < n) ? deg[idx] : 0; s += d[i]; }
    int inc = s;
#pragma unroll
    for (int o = 1; o < 32; o <<= 1) {
        int t = __shfl_up_sync(0xffffffffu, inc, o);
        if (lane >= o) inc += t;
    }
    __shared__ int ws[8];
    if (lane == 31) ws[w] = inc;
    __syncthreads();
    if (w == 0 && lane < 8) {
        int v = ws[lane];
#pragma unroll
        for (int o = 1; o < 8; o <<= 1) {
            int t = __shfl_up_sync(0x000000ffu, v, o);
            if (lane >= o) v += t;
        }
        ws[lane] = v;
    }
    __syncthreads();
    int run = inc - s + (w > 0 ? ws[w - 1] : 0) + bsum[blockIdx.x];
#pragma unroll
    for (int i = 0; i < 4; i++) {
        int idx = base + i;
        if (idx < n) {
            off[idx] = run; cur[idx] = run;
            dinv[idx] = rsqrtf((float)d[i] + 1.0f);
            run += d[i];
            if (idx == n - 1) off[n] = run;
        }
    }
}
__global__ void bucket_kernel(const int* __restrict__ src, const int* __restrict__ dst,
                              int* __restrict__ cur, int* __restrict__ sorted, int E) {
    int t = blockIdx.x * blockDim.x + threadIdx.x;
    int base = t * 4;
    if (base + 3 < E) {
        int4 s = *(const int4*)(src + base);
        int4 d = *(const int4*)(dst + base);
        int p0 = atomicAdd(&cur[d.x], 1);
        int p1 = atomicAdd(&cur[d.y], 1);
        int p2 = atomicAdd(&cur[d.z], 1);
        int p3 = atomicAdd(&cur[d.w], 1);
        sorted[p0] = s.x;
        sorted[p1] = s.y;
        sorted[p2] = s.z;
        sorted[p3] = s.w;
    } else {
        for (int e = base; e < E; e++) {
            int p = atomicAdd(&cur[dst[e]], 1);
            sorted[p] = src[e];
        }
    }
}

// ---------------- fuse heads: Wf = Wp1 @ Wp2, bf = bp1 @ Wp2 + bp2 ----------------
__global__ void fuse_heads_kernel(const float* __restrict__ Wp1, const float* __restrict__ bp1,
                                  const float* __restrict__ Wp2, const float* __restrict__ bp2,
                                  float* __restrict__ Wf, float* __restrict__ bf) {
    int idx = blockIdx.x * blockDim.x + threadIdx.x;
    if (idx < 128 * 64) {
        int i = idx >> 6, j = idx & 63;
        float s = 0.f;
#pragma unroll 8
        for (int k = 0; k < 128; k++)
            s = fmaf(__ldg(&Wp1[i * 128 + k]), __ldg(&Wp2[k * 64 + j]), s);
        Wf[idx] = s;
    } else if (idx < 128 * 64 + 64) {
        int j = idx - 128 * 64;
        float s = __ldg(&bp2[j]);
#pragma unroll 8
        for (int k = 0; k < 128; k++)
            s = fmaf(__ldg(&bp1[k]), __ldg(&Wp2[k * 64 + j]), s);
        bf[j] = s;
    }
}

// ================= HMMA GEMM (mma.sync.m16n8k16), W always split bf16 hi/lo =================
// ABF16=false: A fp32, 3-term split (hh + h*wlo + alo*whi)  -- conv1 (pristine input)
// ABF16=true : A already packed bf16 rows, 2 MMAs (a*whi + a*wlo) -- convs 2/3, head
// MODE 0: zb[row] = (A@W)[row]  (UNSCALED, packed bf16x2; dinv applied in aggregate)
// MODE 2: out[row] = sigmoid((A@W)[row] + bias)  (fp32)
// Epilogue: fragments staged in smem (reusing A region), then coalesced 16B stores.
template <int BN, int MODE, bool ABF16>
__global__ __launch_bounds__(256)
void mma_gemm_kernel(const void* __restrict__ Ain, const float* __restrict__ W,
                     const float* __restrict__ bias,
                     float* __restrict__ out, uint32_t* __restrict__ zb,
                     int M, int ntiles) {
    constexpr int NT = BN / 16;
    constexpr int RS = 272;                // smem row stride bytes (136 bf16 = 17*16B)
    constexpr int WB = BN * RS;
    constexpr int OFF_WHI = 1024;
    constexpr int OFF_WLO = 1024 + WB;
    constexpr int OFF_AHI = 1024 + 2 * WB;
    constexpr int OFF_ALO = OFF_AHI + 128 * RS;   // only used when !ABF16
    constexpr int RSW = 68;                // output staging stride (words); 68%32=4 -> conflict-free

    extern __shared__ char smem[];
    float* sbias = (float*)smem;
    const uint32_t sb = smem_to_u32(smem);
    const int tid = threadIdx.x;
    const int wid = tid >> 5, lane = tid & 31;
    const int wm = wid >> 1;
    const int wn = wid & 1;

    // stage Wt hi/lo once (Wt[n][k]; W input is [k][n] row-major, fp32)
    for (int i = tid; i < BN * 128; i += 256) {
        int nn = i >> 7, k = i & 127;
        float w = __ldg(&W[(size_t)k * BN + nn]);
        __nv_bfloat16 h = __float2bfloat16(w);
        __nv_bfloat16 l = __float2bfloat16(w - __bfloat162float(h));
        *(__nv_bfloat16*)(smem + OFF_WHI + nn * RS + k * 2) = h;
        *(__nv_bfloat16*)(smem + OFF_WLO + nn * RS + k * 2) = l;
    }
    if (MODE == 2 && tid < BN) sbias[tid] = __ldg(&bias[tid]);
    __syncthreads();

    const int arow = wm * 32 + (lane & 7) + ((lane >> 3) & 1) * 8;
    const int acol = ((lane >> 4) & 1) * 8;
    const uint32_t aHi = sb + OFF_AHI + arow * RS + acol * 2;
    const uint32_t aLo = sb + OFF_ALO + arow * RS + acol * 2;
    const int brow = wn * (BN / 2) + (lane & 7) + ((lane >> 4) & 1) * 8;
    const int bcol = ((lane >> 3) & 1) * 8;
    const uint32_t bHi = sb + OFF_WHI + brow * RS + bcol * 2;
    const uint32_t bLo = sb + OFF_WLO + brow * RS + bcol * 2;

    uint32_t* sOut = (uint32_t*)(smem + OFF_AHI);   // reused post-mainloop (128*68 words = 34816B = A region)

    for (int tile = blockIdx.x; tile < ntiles; tile += gridDim.x) {
        const int rowbase = tile * 128;
        __syncthreads();   // prior iteration's smem readers (incl. epilogue LDS) done

        if (ABF16) {
            // A already bf16: copy 128 rows x 256B into sAhi (16B chunks)
            const uint4* Ab = (const uint4*)Ain;
#pragma unroll
            for (int it = 0; it < 8; it++) {
                int i = tid + it * 256;
                int r = i >> 4, c = i & 15;
                int grow = rowbase + r;
                uint4 v = (grow < M) ? __ldg(&Ab[(size_t)grow * 16 + c])
                                     : make_uint4(0u, 0u, 0u, 0u);
                *(uint4*)(smem + OFF_AHI + r * RS + c * 16) = v;
            }
        } else {
            // A fp32: convert to bf16 hi/lo smem
            const float* A = (const float*)Ain;
#pragma unroll
            for (int it = 0; it < 16; it++) {
                int i = tid + it * 256;
                int r = i >> 5, c4 = i & 31;
                int grow = rowbase + r;
                float4 v = (grow < M) ? ((const float4*)(A + (size_t)grow * 128))[c4]
                                      : make_float4(0.f, 0.f, 0.f, 0.f);
                uint32_t h01, h23, l01, l23;
                CVT_PACK(h01, v.y, v.x);
                float r0 = v.x - __uint_as_float(h01 << 16);
                float r1 = v.y - __uint_as_float(h01 & 0xffff0000u);
                CVT_PACK(l01, r1, r0);
                CVT_PACK(h23, v.w, v.z);
                float r2 = v.z - __uint_as_float(h23 << 16);
                float r3 = v.w - __uint_as_float(h23 & 0xffff0000u);
                CVT_PACK(l23, r3, r2);
                *(uint2*)(smem + OFF_AHI + r * RS + c4 * 8) = make_uint2(h01, h23);
                *(uint2*)(smem + OFF_ALO + r * RS + c4 * 8) = make_uint2(l01, l23);
            }
        }
        __syncthreads();

        float c[2][NT][4];
#pragma unroll
        for (int mt = 0; mt < 2; mt++)
#pragma unroll
            for (int nt = 0; nt < NT; nt++)
#pragma unroll
                for (int j = 0; j < 4; j++) c[mt][nt][j] = 0.f;

#pragma unroll
        for (int ks = 0; ks < 8; ks++) {
            uint32_t ahi[2][4], alo[2][4];
#pragma unroll
            for (int mt = 0; mt < 2; mt++) {
                ldsm_x4(ahi[mt], aHi + mt * (16 * RS) + ks * 32);
                if (!ABF16) ldsm_x4(alo[mt], aLo + mt * (16 * RS) + ks * 32);
            }
            uint32_t bhi[NT][2], blo[NT][2];
#pragma unroll
            for (int g = 0; g < NT / 2; g++) {
                uint32_t r4[4];
                ldsm_x4(r4, bHi + g * (16 * RS) + ks * 32);
                bhi[2 * g][0] = r4[0]; bhi[2 * g][1] = r4[1];
                bhi[2 * g + 1][0] = r4[2]; bhi[2 * g + 1][1] = r4[3];
                ldsm_x4(r4, bLo + g * (16 * RS) + ks * 32);
                blo[2 * g][0] = r4[0]; blo[2 * g][1] = r4[1];
                blo[2 * g + 1][0] = r4[2]; blo[2 * g + 1][1] = r4[3];
            }
#pragma unroll
            for (int mt = 0; mt < 2; mt++)
#pragma unroll
                for (int nt = 0; nt < NT; nt++) {
                    mma16816(c[mt][nt], ahi[mt], bhi[nt]);
                    mma16816(c[mt][nt], ahi[mt], blo[nt]);
                    if (!ABF16) mma16816(c[mt][nt], alo[mt], bhi[nt]);
                }
        }

        // ---- epilogue: stage fragments in smem, then coalesced 16B global stores ----
        __syncthreads();   // all warps done reading A region before reuse
        {
            const int rowt = lane >> 2;
            const int colp = (lane & 3) * 2;
#pragma unroll
            for (int mt = 0; mt < 2; mt++) {
#pragma unroll
                for (int h = 0; h < 2; h++) {
                    const int lrow = wm * 32 + mt * 16 + h * 8 + rowt;   // 0..127
#pragma unroll
                    for (int nt = 0; nt < NT; nt++) {
                        float v0 = c[mt][nt][2 * h], v1 = c[mt][nt][2 * h + 1];
                        if (MODE == 0) {
                            // word index = col pair: wn*32 + nt*4 + (lane&3); bank = 4*rowt + (lane&3): conflict-free
                            uint32_t p;
                            CVT_PACK(p, v1, v0);
                            sOut[lrow * RSW + wn * (BN / 4) + nt * 4 + (lane & 3)] = p;
                        } else {
                            const int nn = wn * (BN / 2) + nt * 8 + colp;
                            float t0 = v0 + sbias[nn], t1 = v1 + sbias[nn + 1];
                            float2 sv = make_float2(1.f / (1.f + __expf(-t0)),
                                                    1.f / (1.f + __expf(-t1)));
                            *(float2*)&sOut[lrow * RSW + nn] = sv;
                        }
                    }
                }
            }
        }
        __syncthreads();
        {
            // 2 threads per row, 32 words (128B) each -> 8x LDS.128 + STG.128
            const int r = tid >> 1, half = tid & 1;
            const int grow = rowbase + r;
            if (grow < M) {
                const uint4* s4 = (const uint4*)&sOut[r * RSW + half * 32];
                uint4* d4 = (MODE == 0)
                    ? (uint4*)&zb[(size_t)grow * 64 + half * 32]
                    : (uint4*)(out + (size_t)grow * BN + half * 32);
#pragma unroll
                for (int i = 0; i < 8; i++) d4[i] = s4[i];
            }
        }
    }
}

// -------- fused CSR aggregate (bf16 gather, per-edge dinv[src], fp32 accum)
//          + self-loop + dinv[dst] + bias + ReLU (+LN), bf16 packed output --------
template <int DO_LN>
__global__ __launch_bounds__(256)
void aggregate_kernel(const uint2* __restrict__ z, const int* __restrict__ off,
                      const int* __restrict__ srcs, const float* __restrict__ dinv,
                      const float* __restrict__ b, const float* __restrict__ g,
                      const float* __restrict__ be, uint2* __restrict__ out, int n) {
    const int warp = (blockIdx.x * blockDim.x + threadIdx.x) >> 5;
    const int lane = threadIdx.x & 31;
    if (warp >= n) return;

    const int s0 = __ldg(&off[warp]);
    const int s1 = __ldg(&off[warp + 1]);
    const float dv = __ldg(&dinv[warp]);

    // self loop: dinv[i] * z_i (z is unscaled)
    float4 zs = unpack_bf4(__ldg(&z[(size_t)warp * 32 + lane]));
    float4 acc = make_float4(dv * zs.x, dv * zs.y, dv * zs.z, dv * zs.w);

    for (int base = s0; base < s1; base += 32) {
        const int cnt = min(32, s1 - base);
        const bool val = (base + lane < s1);
        int mys = val ? __ldg(&srcs[base + lane]) : 0;
        float myd = val ? __ldg(&dinv[mys]) : 0.f;
#pragma unroll 8
        for (int j = 0; j < cnt; j++) {
            int sn = __shfl_sync(0xffffffffu, mys, j);
            float ds = __shfl_sync(0xffffffffu, myd, j);
            float4 v = unpack_bf4(__ldg(&z[(size_t)sn * 32 + lane]));
            acc.x = fmaf(ds, v.x, acc.x);
            acc.y = fmaf(ds, v.y, acc.y);
            acc.z = fmaf(ds, v.z, acc.z);
            acc.w = fmaf(ds, v.w, acc.w);
        }
    }

    const float4 bb = ((const float4*)b)[lane];
    float4 v = make_float4(fmaxf(fmaf(dv, acc.x, bb.x), 0.f),
                           fmaxf(fmaf(dv, acc.y, bb.y), 0.f),
                           fmaxf(fmaf(dv, acc.z, bb.z), 0.f),
                           fmaxf(fmaf(dv, acc.w, bb.w), 0.f));
    if (DO_LN) {
        float s = v.x + v.y + v.z + v.w;
#pragma unroll
        for (int o = 16; o > 0; o >>= 1) s += __shfl_xor_sync(0xffffffffu, s, o);
        const float mu = s * (1.f / 128.f);
        float4 xc = make_float4(v.x - mu, v.y - mu, v.z - mu, v.w - mu);
        float s2 = xc.x * xc.x + xc.y * xc.y + xc.z * xc.z + xc.w * xc.w;
#pragma unroll
        for (int o = 16; o > 0; o >>= 1) s2 += __shfl_xor_sync(0xffffffffu, s2, o);
        const float rs = rsqrtf(s2 * (1.f / 128.f) + LN_EPS);
        const float4 gg = ((const float4*)g)[lane];
        const float4 ee = ((const float4*)be)[lane];
        v = make_float4(fmaf(gg.x * xc.x, rs, ee.x), fmaf(gg.y * xc.y, rs, ee.y),
                        fmaf(gg.z * xc.z, rs, ee.z), fmaf(gg.w * xc.w, rs, ee.w));
    }
    uint2 p;
    CVT_PACK(p.x, v.y, v.x);
    CVT_PACK(p.y, v.w, v.z);
    out[(size_t)warp * 32 + lane] = p;
}

// ---------------- launch ----------------
extern "C" void kernel_launch(void* const* d_in, const int* in_sizes, int n_in,
                              void* d_out, int out_size) {
    const float* x   = (const float*)d_in[0];
    const int*   ei  = (const int*)  d_in[1];
    const float* W1  = (const float*)d_in[2];
    const float* b1  = (const float*)d_in[3];
    const float* W2  = (const float*)d_in[4];
    const float* b2  = (const float*)d_in[5];
    const float* W3  = (const float*)d_in[6];
    const float* b3  = (const float*)d_in[7];
    const float* g1  = (const float*)d_in[8];
    const float* be1 = (const float*)d_in[9];
    const float* g2  = (const float*)d_in[10];
    const float* be2 = (const float*)d_in[11];
    const float* Wp1 = (const float*)d_in[12];
    const float* bp1 = (const float*)d_in[13];
    const float* Wp2 = (const float*)d_in[14];
    const float* bp2 = (const float*)d_in[15];
    float* out = (float*)d_out;

    const int n = in_sizes[0] / DIM;          // 100000
    const int E = in_sizes[1] / 2;            // 1600000
    const int* src = ei;
    const int* dst = ei + E;

    int *deg, *off, *cur, *srcs, *bsum;
    float *dinv, *Wf, *bf;
    uint32_t *zb, *hb;
    cudaGetSymbolAddress((void**)&deg,  g_deg);
    cudaGetSymbolAddress((void**)&off,  g_off);
    cudaGetSymbolAddress((void**)&cur,  g_cur);
    cudaGetSymbolAddress((void**)&srcs, g_srcs);
    cudaGetSymbolAddress((void**)&bsum, g_bsum);
    cudaGetSymbolAddress((void**)&dinv, g_dinv);
    cudaGetSymbolAddress((void**)&zb,   g_zb);
    cudaGetSymbolAddress((void**)&hb,   g_hb);
    cudaGetSymbolAddress((void**)&Wf,   g_Wf);
    cudaGetSymbolAddress((void**)&bf,   g_bf);

    // smem sizes: header 1024 + 2 W splits + A (1 or 2 splits), RS=272
    const int SM128_FP = 1024 + 2 * (128 * 272) + 2 * (128 * 272);  // 140288 (conv1)
    const int SM128_BF = 1024 + 2 * (128 * 272) + 1 * (128 * 272);  // 105472 (convs 2/3)
    const int SM64_BF  = 1024 + 2 * (64 * 272)  + 1 * (128 * 272);  //  70656 (head)
    cudaFuncSetAttribute(mma_gemm_kernel<128, 0, false>, cudaFuncAttributeMaxDynamicSharedMemorySize, SM128_FP);
    cudaFuncSetAttribute(mma_gemm_kernel<128, 0, true>,  cudaFuncAttributeMaxDynamicSharedMemorySize, SM128_BF);
    cudaFuncSetAttribute(mma_gemm_kernel<64,  2, true>,  cudaFuncAttributeMaxDynamicSharedMemorySize, SM64_BF);

    const int ntiles = (n + 127) / 128;              // 782
    const int GEMM_GRID = 148;                       // conv1 (1 CTA/SM, 140KB smem)
    const int GEMM_GRID2 = 296;                      // bf16-A GEMMs (2 CTAs/SM)
    const int agg_grid = (n * 32 + 255) / 256;
    const int nscan = (n + 1023) / 1024;
    const int e4_grid = (E / 4 + 255) / 256;         // 4 edges per thread

    // lazily-created secondary stream + fork/join events (no device allocation;
    // identical launched work every call)
    static cudaStream_t s2 = nullptr;
    static cudaEvent_t evA = nullptr, evB = nullptr;
    if (s2 == nullptr) {
        cudaStreamCreateWithFlags(&s2, cudaStreamNonBlocking);
        cudaEventCreateWithFlags(&evA, cudaEventDisableTiming);
        cudaEventCreateWithFlags(&evB, cudaEventDisableTiming);
    }

    // ---- fork: branch B (fuse_heads + conv1 GEMM, independent of CSR) on s2 ----
    cudaEventRecord(evA, 0);
    cudaStreamWaitEvent(s2, evA, 0);
    fuse_heads_kernel<<<33, 256, 0, s2>>>(Wp1, bp1, Wp2, bp2, Wf, bf);
    mma_gemm_kernel<128, 0, false><<<GEMM_GRID, 256, SM128_FP, s2>>>(x, W1, nullptr, nullptr, zb, n, ntiles);
    cudaEventRecord(evB, s2);

    // ---- branch A: CSR build on default stream (concurrent with branch B) ----
    zero_deg_kernel<<<(n + 255) / 256, 256>>>(deg, n);
    hist_kernel<<<e4_grid, 256>>>(dst, deg, E);
    scan_part_kernel <<<nscan, 256>>>(deg, bsum, n);
    scan_block_kernel<<<1, 128>>>(bsum, nscan);
    scan_final_kernel<<<nscan, 256>>>(deg, bsum, off, cur, dinv, n);
    bucket_kernel<<<e4_grid, 256>>>(src, dst, cur, srcs, E);

    // ---- join ----
    cudaStreamWaitEvent(0, evB, 0);

    // ---- conv1 aggregate ----
    aggregate_kernel<1><<<agg_grid, 256>>>((const uint2*)zb, off, srcs, dinv, b1, g1, be1, (uint2*)hb, n);

    // ---- conv2 (bf16 A) ----
    mma_gemm_kernel<128, 0, true><<<GEMM_GRID2, 256, SM128_BF>>>(hb, W2, nullptr, nullptr, zb, n, ntiles);
    aggregate_kernel<1><<<agg_grid, 256>>>((const uint2*)zb, off, srcs, dinv, b2, g2, be2, (uint2*)hb, n);

    // ---- conv3 (bf16 A, no LN) ----
    mma_gemm_kernel<128, 0, true><<<GEMM_GRID2, 256, SM128_BF>>>(hb, W3, nullptr, nullptr, zb, n, ntiles);
    aggregate_kernel<0><<<agg_grid, 256>>>((const uint2*)zb, off, srcs, dinv, b3, nullptr, nullptr, (uint2*)hb, n);

    // ---- fused head: out = sigmoid(h @ Wf + bf) (bf16 A) ----
    mma_gemm_kernel<64, 2, true><<<GEMM_GRID2, 256, SM64_BF>>>(hb, Wf, bf, out, nullptr, n, ntiles);
}

// round 17
// speedup vs baseline: 1.0866x; 1.0866x over previous
#include <cuda_runtime.h>
#include <cuda_bf16.h>
#include <math.h>
#include <stdint.h>

#define NMAX 100000
#define EMAX 2000000
#define DIM 128
#define LN_EPS 1e-5f

// ---------------- helpers ----------------
__device__ __forceinline__ uint32_t smem_to_u32(const void* p) {
    uint32_t a;
    asm("{ .reg .u64 t; cvta.to.shared.u64 t, %1; cvt.u32.u64 %0, t; }" : "=r"(a) : "l"(p));
    return a;
}
// pack two fp32 -> bf16x2 (up -> high 16 bits, low -> low 16 bits)
#define CVT_PACK(res, up, low) \
    asm("cvt.rn.bf16x2.f32 %0, %1, %2;" : "=r"(res) : "f"(up), "f"(low))

__device__ __forceinline__ void ldsm_x4(uint32_t* r, uint32_t addr) {
    asm volatile("ldmatrix.sync.aligned.m8n8.x4.shared.b16 {%0,%1,%2,%3}, [%4];"
                 : "=r"(r[0]), "=r"(r[1]), "=r"(r[2]), "=r"(r[3]) : "r"(addr));
}
__device__ __forceinline__ void mma16816(float* c, const uint32_t* a, const uint32_t* b) {
    asm volatile("mma.sync.aligned.m16n8k16.row.col.f32.bf16.bf16.f32 "
                 "{%0,%1,%2,%3}, {%4,%5,%6,%7}, {%8,%9}, {%0,%1,%2,%3};"
                 : "+f"(c[0]), "+f"(c[1]), "+f"(c[2]), "+f"(c[3])
                 : "r"(a[0]), "r"(a[1]), "r"(a[2]), "r"(a[3]), "r"(b[0]), "r"(b[1]));
}
// exact bf16x2 -> 2x fp32 (bf16 bits are the top 16 of fp32; low half = lower index)
__device__ __forceinline__ float4 unpack_bf4(uint2 u) {
    return make_float4(__uint_as_float(u.x << 16), __uint_as_float(u.x & 0xffff0000u),
                       __uint_as_float(u.y << 16), __uint_as_float(u.y & 0xffff0000u));
}

// ---------------- static scratch ----------------
__device__ int      g_deg [NMAX];
__device__ int      g_off [NMAX + 1];
__device__ int      g_cur [NMAX];
__device__ int      g_srcs[EMAX];
__device__ int      g_bsum[256];
__device__ float    g_dinv[NMAX];
__device__ float    g_Wf  [DIM * 64];
__device__ float    g_bf  [64];
__device__ uint32_t g_zb  [(size_t)NMAX * 64];   // z packed bf16x2 (conv1: unscaled; convs2/3: *dinv[row])
__device__ uint32_t g_hb  [(size_t)NMAX * 64];   // h (activations) packed bf16x2

// ---------------- CSR build ----------------
__global__ void zero_deg_kernel(int* __restrict__ deg, int n) {
    int i = blockIdx.x * blockDim.x + threadIdx.x;
    if (i < n) deg[i] = 0;
}
__global__ void hist_kernel(const int* __restrict__ dst, int* __restrict__ deg, int E) {
    int t = blockIdx.x * blockDim.x + threadIdx.x;
    int base = t * 4;
    if (base + 3 < E) {
        int4 d = *(const int4*)(dst + base);
        atomicAdd(&deg[d.x], 1);
        atomicAdd(&deg[d.y], 1);
        atomicAdd(&deg[d.z], 1);
        atomicAdd(&deg[d.w], 1);
    } else {
        for (int e = base; e < E; e++) atomicAdd(&deg[dst[e]], 1);
    }
}
__global__ __launch_bounds__(256)
void scan_part_kernel(const int* __restrict__ deg, int* __restrict__ bsum, int n) {
    const int tid = threadIdx.x;
    const int base = blockIdx.x * 1024 + tid * 4;
    int s = 0;
#pragma unroll
    for (int i = 0; i < 4; i++) { int idx = base + i; if (idx < n) s += deg[idx]; }
#pragma unroll
    for (int o = 16; o > 0; o >>= 1) s += __shfl_xor_sync(0xffffffffu, s, o);
    __shared__ int ws[8];
    if ((tid & 31) == 0) ws[tid >> 5] = s;
    __syncthreads();
    if (tid == 0) {
        int t = 0;
#pragma unroll
        for (int i = 0; i < 8; i++) t += ws[i];
        bsum[blockIdx.x] = t;
    }
}
__global__ __launch_bounds__(128)
void scan_block_kernel(int* __restrict__ bsum, int nb) {
    __shared__ int sh[128];
    const int tid = threadIdx.x;
    int v = (tid < nb) ? bsum[tid] : 0;
    sh[tid] = v;
    __syncthreads();
    for (int o = 1; o < 128; o <<= 1) {
        int t = (tid >= o) ? sh[tid - o] : 0;
        __syncthreads();
        sh[tid] += t;
        __syncthreads();
    }
    if (tid < nb) bsum[tid] = sh[tid] - v;
}
__global__ __launch_bounds__(256)
void scan_final_kernel(const int* __restrict__ deg, const int* __restrict__ bsum,
                       int* __restrict__ off, int* __restrict__ cur,
                       float* __restrict__ dinv, int n) {
    const int tid = threadIdx.x;
    const int lane = tid & 31, w = tid >> 5;
    const int base = blockIdx.x * 1024 + tid * 4;
    int d[4]; int s = 0;
#pragma unroll
    for (int i = 0; i < 4; i++) { int idx = base + i; d[i] = (idx < n) ? deg[idx] : 0; s += d[i]; }
    int inc = s;
#pragma unroll
    for (int o = 1; o < 32; o <<= 1) {
        int t = __shfl_up_sync(0xffffffffu, inc, o);
        if (lane >= o) inc += t;
    }
    __shared__ int ws[8];
    if (lane == 31) ws[w] = inc;
    __syncthreads();
    if (w == 0 && lane < 8) {
        int v = ws[lane];
#pragma unroll
        for (int o = 1; o < 8; o <<= 1) {
            int t = __shfl_up_sync(0x000000ffu, v, o);
            if (lane >= o) v += t;
        }
        ws[lane] = v;
    }
    __syncthreads();
    int run = inc - s + (w > 0 ? ws[w - 1] : 0) + bsum[blockIdx.x];
#pragma unroll
    for (int i = 0; i < 4; i++) {
        int idx = base + i;
        if (idx < n) {
            off[idx] = run; cur[idx] = run;
            dinv[idx] = rsqrtf((float)d[i] + 1.0f);
            run += d[i];
            if (idx == n - 1) off[n] = run;
        }
    }
}
__global__ void bucket_kernel(const int* __restrict__ src, const int* __restrict__ dst,
                              int* __restrict__ cur, int* __restrict__ sorted, int E) {
    int t = blockIdx.x * blockDim.x + threadIdx.x;
    int base = t * 4;
    if (base + 3 < E) {
        int4 s = *(const int4*)(src + base);
        int4 d = *(const int4*)(dst + base);
        int p0 = atomicAdd(&cur[d.x], 1);
        int p1 = atomicAdd(&cur[d.y], 1);
        int p2 = atomicAdd(&cur[d.z], 1);
        int p3 = atomicAdd(&cur[d.w], 1);
        sorted[p0] = s.x;
        sorted[p1] = s.y;
        sorted[p2] = s.z;
        sorted[p3] = s.w;
    } else {
        for (int e = base; e < E; e++) {
            int p = atomicAdd(&cur[dst[e]], 1);
            sorted[p] = src[e];
        }
    }
}

// ---------------- fuse heads: Wf = Wp1 @ Wp2, bf = bp1 @ Wp2 + bp2 ----------------
__global__ void fuse_heads_kernel(const float* __restrict__ Wp1, const float* __restrict__ bp1,
                                  const float* __restrict__ Wp2, const float* __restrict__ bp2,
                                  float* __restrict__ Wf, float* __restrict__ bf) {
    int idx = blockIdx.x * blockDim.x + threadIdx.x;
    if (idx < 128 * 64) {
        int i = idx >> 6, j = idx & 63;
        float s = 0.f;
#pragma unroll 8
        for (int k = 0; k < 128; k++)
            s = fmaf(__ldg(&Wp1[i * 128 + k]), __ldg(&Wp2[k * 64 + j]), s);
        Wf[idx] = s;
    } else if (idx < 128 * 64 + 64) {
        int j = idx - 128 * 64;
        float s = __ldg(&bp2[j]);
#pragma unroll 8
        for (int k = 0; k < 128; k++)
            s = fmaf(__ldg(&bp1[k]), __ldg(&Wp2[k * 64 + j]), s);
        bf[j] = s;
    }
}

// ================= HMMA GEMM (mma.sync.m16n8k16), W always split bf16 hi/lo =================
// ABF16=false: A fp32, 3-term split (hh + h*wlo + alo*whi)  -- conv1 (pristine input)
// ABF16=true : A already packed bf16 rows, 2 MMAs (a*whi + a*wlo) -- convs 2/3, head
// MODE 0: zb[row] = (A@W)[row] [* dinv[row] if dinv != nullptr]  (packed bf16x2)
// MODE 2: out[row] = sigmoid((A@W)[row] + bias)  (fp32)
template <int BN, int MODE, bool ABF16>
__global__ __launch_bounds__(256)
void mma_gemm_kernel(const void* __restrict__ Ain, const float* __restrict__ W,
                     const float* __restrict__ bias, const float* __restrict__ dinv,
                     float* __restrict__ out, uint32_t* __restrict__ zb,
                     int M, int ntiles) {
    constexpr int NT = BN / 16;
    constexpr int RS = 272;                // smem row stride bytes (136 bf16 = 17*16B)
    constexpr int WB = BN * RS;
    constexpr int OFF_WHI = 1024;
    constexpr int OFF_WLO = 1024 + WB;
    constexpr int OFF_AHI = 1024 + 2 * WB;
    constexpr int OFF_ALO = OFF_AHI + 128 * RS;   // only used when !ABF16

    extern __shared__ char smem[];
    float* sbias = (float*)smem;
    const uint32_t sb = smem_to_u32(smem);
    const int tid = threadIdx.x;
    const int wid = tid >> 5, lane = tid & 31;
    const int wm = wid >> 1;
    const int wn = wid & 1;

    // stage Wt hi/lo once (Wt[n][k]; W input is [k][n] row-major, fp32)
    for (int i = tid; i < BN * 128; i += 256) {
        int nn = i >> 7, k = i & 127;
        float w = __ldg(&W[(size_t)k * BN + nn]);
        __nv_bfloat16 h = __float2bfloat16(w);
        __nv_bfloat16 l = __float2bfloat16(w - __bfloat162float(h));
        *(__nv_bfloat16*)(smem + OFF_WHI + nn * RS + k * 2) = h;
        *(__nv_bfloat16*)(smem + OFF_WLO + nn * RS + k * 2) = l;
    }
    if (MODE == 2 && tid < BN) sbias[tid] = __ldg(&bias[tid]);
    __syncthreads();

    const int arow = wm * 32 + (lane & 7) + ((lane >> 3) & 1) * 8;
    const int acol = ((lane >> 4) & 1) * 8;
    const uint32_t aHi = sb + OFF_AHI + arow * RS + acol * 2;
    const uint32_t aLo = sb + OFF_ALO + arow * RS + acol * 2;
    const int brow = wn * (BN / 2) + (lane & 7) + ((lane >> 4) & 1) * 8;
    const int bcol = ((lane >> 3) & 1) * 8;
    const uint32_t bHi = sb + OFF_WHI + brow * RS + bcol * 2;
    const uint32_t bLo = sb + OFF_WLO + brow * RS + bcol * 2;

    for (int tile = blockIdx.x; tile < ntiles; tile += gridDim.x) {
        const int rowbase = tile * 128;
        __syncthreads();

        if (ABF16) {
            // A already bf16: copy 128 rows x 256B into sAhi (16B chunks)
            const uint4* Ab = (const uint4*)Ain;
#pragma unroll
            for (int it = 0; it < 8; it++) {
                int i = tid + it * 256;
                int r = i >> 4, c = i & 15;
                int grow = rowbase + r;
                uint4 v = (grow < M) ? __ldg(&Ab[(size_t)grow * 16 + c])
                                     : make_uint4(0u, 0u, 0u, 0u);
                *(uint4*)(smem + OFF_AHI + r * RS + c * 16) = v;
            }
        } else {
            // A fp32: convert to bf16 hi/lo smem
            const float* A = (const float*)Ain;
#pragma unroll
            for (int it = 0; it < 16; it++) {
                int i = tid + it * 256;
                int r = i >> 5, c4 = i & 31;
                int grow = rowbase + r;
                float4 v = (grow < M) ? ((const float4*)(A + (size_t)grow * 128))[c4]
                                      : make_float4(0.f, 0.f, 0.f, 0.f);
                uint32_t h01, h23, l01, l23;
                CVT_PACK(h01, v.y, v.x);
                float r0 = v.x - __uint_as_float(h01 << 16);
                float r1 = v.y - __uint_as_float(h01 & 0xffff0000u);
                CVT_PACK(l01, r1, r0);
                CVT_PACK(h23, v.w, v.z);
                float r2 = v.z - __uint_as_float(h23 << 16);
                float r3 = v.w - __uint_as_float(h23 & 0xffff0000u);
                CVT_PACK(l23, r3, r2);
                *(uint2*)(smem + OFF_AHI + r * RS + c4 * 8) = make_uint2(h01, h23);
                *(uint2*)(smem + OFF_ALO + r * RS + c4 * 8) = make_uint2(l01, l23);
            }
        }
        __syncthreads();

        float c[2][NT][4];
#pragma unroll
        for (int mt = 0; mt < 2; mt++)
#pragma unroll
            for (int nt = 0; nt < NT; nt++)
#pragma unroll
                for (int j = 0; j < 4; j++) c[mt][nt][j] = 0.f;

#pragma unroll
        for (int ks = 0; ks < 8; ks++) {
            uint32_t ahi[2][4], alo[2][4];
#pragma unroll
            for (int mt = 0; mt < 2; mt++) {
                ldsm_x4(ahi[mt], aHi + mt * (16 * RS) + ks * 32);
                if (!ABF16) ldsm_x4(alo[mt], aLo + mt * (16 * RS) + ks * 32);
            }
            uint32_t bhi[NT][2], blo[NT][2];
#pragma unroll
            for (int g = 0; g < NT / 2; g++) {
                uint32_t r4[4];
                ldsm_x4(r4, bHi + g * (16 * RS) + ks * 32);
                bhi[2 * g][0] = r4[0]; bhi[2 * g][1] = r4[1];
                bhi[2 * g + 1][0] = r4[2]; bhi[2 * g + 1][1] = r4[3];
                ldsm_x4(r4, bLo + g * (16 * RS) + ks * 32);
                blo[2 * g][0] = r4[0]; blo[2 * g][1] = r4[1];
                blo[2 * g + 1][0] = r4[2]; blo[2 * g + 1][1] = r4[3];
            }
#pragma unroll
            for (int mt = 0; mt < 2; mt++)
#pragma unroll
                for (int nt = 0; nt < NT; nt++) {
                    mma16816(c[mt][nt], ahi[mt], bhi[nt]);
                    mma16816(c[mt][nt], ahi[mt], blo[nt]);
                    if (!ABF16) mma16816(c[mt][nt], alo[mt], bhi[nt]);
                }
        }

        const int rowt = lane >> 2;
        const int colp = (lane & 3) * 2;
#pragma unroll
        for (int mt = 0; mt < 2; mt++) {
#pragma unroll
            for (int h = 0; h < 2; h++) {
                const int row = rowbase + wm * 32 + mt * 16 + h * 8 + rowt;
                if (row < M) {
                    const float sc = (MODE == 0 && dinv != nullptr) ? __ldg(&dinv[row]) : 1.f;
#pragma unroll
                    for (int nt = 0; nt < NT; nt++) {
                        const int nn = wn * (BN / 2) + nt * 8 + colp;
                        float v0 = c[mt][nt][2 * h], v1 = c[mt][nt][2 * h + 1];
                        if (MODE == 0) {
                            uint32_t p;
                            CVT_PACK(p, v1 * sc, v0 * sc);
                            zb[(size_t)row * 64 + (nn >> 1)] = p;
                        } else {
                            float t0 = v0 + sbias[nn], t1 = v1 + sbias[nn + 1];
                            float2* o = (float2*)(out + (size_t)row * BN + nn);
                            *o = make_float2(1.f / (1.f + __expf(-t0)),
                                             1.f / (1.f + __expf(-t1)));
                        }
                    }
                }
            }
        }
    }
}

// -------- fused CSR aggregate (bf16 gather, fp32 accum) + self-loop + dinv[dst] + bias
//          + ReLU (+LN), bf16 packed output.
// ZSCALED=true : z rows already carry dinv[src] (convs 2/3) -> plain sum
// ZSCALED=false: z unscaled (conv1) -> per-edge dinv[src] FMA
template <int DO_LN, bool ZSCALED>
__global__ __launch_bounds__(256)
void aggregate_kernel(const uint2* __restrict__ z, const int* __restrict__ off,
                      const int* __restrict__ srcs, const float* __restrict__ dinv,
                      const float* __restrict__ b, const float* __restrict__ g,
                      const float* __restrict__ be, uint2* __restrict__ out, int n) {
    const int warp = (blockIdx.x * blockDim.x + threadIdx.x) >> 5;
    const int lane = threadIdx.x & 31;
    if (warp >= n) return;

    const int s0 = __ldg(&off[warp]);
    const int s1 = __ldg(&off[warp + 1]);
    const float dv = __ldg(&dinv[warp]);

    float4 acc;
    {
        float4 zs = unpack_bf4(__ldg(&z[(size_t)warp * 32 + lane]));
        if (ZSCALED) {
            acc = zs;                               // z already has dinv[row] (self loop term)
        } else {
            acc = make_float4(dv * zs.x, dv * zs.y, dv * zs.z, dv * zs.w);
        }
    }

    for (int base = s0; base < s1; base += 32) {
        const int cnt = min(32, s1 - base);
        const bool val = (base + lane < s1);
        int mys = val ? __ldg(&srcs[base + lane]) : 0;
        float myd = (!ZSCALED && val) ? __ldg(&dinv[mys]) : 0.f;
#pragma unroll 8
        for (int j = 0; j < cnt; j++) {
            int sn = __shfl_sync(0xffffffffu, mys, j);
            float4 v = unpack_bf4(__ldg(&z[(size_t)sn * 32 + lane]));
            if (ZSCALED) {
                acc.x += v.x; acc.y += v.y; acc.z += v.z; acc.w += v.w;
            } else {
                float ds = __shfl_sync(0xffffffffu, myd, j);
                acc.x = fmaf(ds, v.x, acc.x);
                acc.y = fmaf(ds, v.y, acc.y);
                acc.z = fmaf(ds, v.z, acc.z);
                acc.w = fmaf(ds, v.w, acc.w);
            }
        }
    }

    const float4 bb = ((const float4*)b)[lane];
    float4 v = make_float4(fmaxf(fmaf(dv, acc.x, bb.x), 0.f),
                           fmaxf(fmaf(dv, acc.y, bb.y), 0.f),
                           fmaxf(fmaf(dv, acc.z, bb.z), 0.f),
                           fmaxf(fmaf(dv, acc.w, bb.w), 0.f));
    if (DO_LN) {
        float s = v.x + v.y + v.z + v.w;
#pragma unroll
        for (int o = 16; o > 0; o >>= 1) s += __shfl_xor_sync(0xffffffffu, s, o);
        const float mu = s * (1.f / 128.f);
        float4 xc = make_float4(v.x - mu, v.y - mu, v.z - mu, v.w - mu);
        float s2 = xc.x * xc.x + xc.y * xc.y + xc.z * xc.z + xc.w * xc.w;
#pragma unroll
        for (int o = 16; o > 0; o >>= 1) s2 += __shfl_xor_sync(0xffffffffu, s2, o);
        const float rs = rsqrtf(s2 * (1.f / 128.f) + LN_EPS);
        const float4 gg = ((const float4*)g)[lane];
        const float4 ee = ((const float4*)be)[lane];
        v = make_float4(fmaf(gg.x * xc.x, rs, ee.x), fmaf(gg.y * xc.y, rs, ee.y),
                        fmaf(gg.z * xc.z, rs, ee.z), fmaf(gg.w * xc.w, rs, ee.w));
    }
    uint2 p;
    CVT_PACK(p.x, v.y, v.x);
    CVT_PACK(p.y, v.w, v.z);
    out[(size_t)warp * 32 + lane] = p;
}

// ---------------- launch ----------------
extern "C" void kernel_launch(void* const* d_in, const int* in_sizes, int n_in,
                              void* d_out, int out_size) {
    const float* x   = (const float*)d_in[0];
    const int*   ei  = (const int*)  d_in[1];
    const float* W1  = (const float*)d_in[2];
    const float* b1  = (const float*)d_in[3];
    const float* W2  = (const float*)d_in[4];
    const float* b2  = (const float*)d_in[5];
    const float* W3  = (const float*)d_in[6];
    const float* b3  = (const float*)d_in[7];
    const float* g1  = (const float*)d_in[8];
    const float* be1 = (const float*)d_in[9];
    const float* g2  = (const float*)d_in[10];
    const float* be2 = (const float*)d_in[11];
    const float* Wp1 = (const float*)d_in[12];
    const float* bp1 = (const float*)d_in[13];
    const float* Wp2 = (const float*)d_in[14];
    const float* bp2 = (const float*)d_in[15];
    float* out = (float*)d_out;

    const int n = in_sizes[0] / DIM;          // 100000
    const int E = in_sizes[1] / 2;            // 1600000
    const int* src = ei;
    const int* dst = ei + E;

    int *deg, *off, *cur, *srcs, *bsum;
    float *dinv, *Wf, *bf;
    uint32_t *zb, *hb;
    cudaGetSymbolAddress((void**)&deg,  g_deg);
    cudaGetSymbolAddress((void**)&off,  g_off);
    cudaGetSymbolAddress((void**)&cur,  g_cur);
    cudaGetSymbolAddress((void**)&srcs, g_srcs);
    cudaGetSymbolAddress((void**)&bsum, g_bsum);
    cudaGetSymbolAddress((void**)&dinv, g_dinv);
    cudaGetSymbolAddress((void**)&zb,   g_zb);
    cudaGetSymbolAddress((void**)&hb,   g_hb);
    cudaGetSymbolAddress((void**)&Wf,   g_Wf);
    cudaGetSymbolAddress((void**)&bf,   g_bf);

    // smem sizes: header 1024 + 2 W splits + A (1 or 2 splits), RS=272
    const int SM128_FP = 1024 + 2 * (128 * 272) + 2 * (128 * 272);  // 140288 (conv1)
    const int SM128_BF = 1024 + 2 * (128 * 272) + 1 * (128 * 272);  // 105472 (convs 2/3)
    const int SM64_BF  = 1024 + 2 * (64 * 272)  + 1 * (128 * 272);  //  70656 (head)
    cudaFuncSetAttribute(mma_gemm_kernel<128, 0, false>, cudaFuncAttributeMaxDynamicSharedMemorySize, SM128_FP);
    cudaFuncSetAttribute(mma_gemm_kernel<128, 0, true>,  cudaFuncAttributeMaxDynamicSharedMemorySize, SM128_BF);
    cudaFuncSetAttribute(mma_gemm_kernel<64,  2, true>,  cudaFuncAttributeMaxDynamicSharedMemorySize, SM64_BF);

    const int ntiles = (n + 127) / 128;              // 782
    const int GEMM_GRID = 148;                       // conv1 (1 CTA/SM, 140KB smem)
    const int GEMM_GRID2 = 296;                      // bf16-A GEMMs (2 CTAs/SM)
    const int agg_grid = (n * 32 + 255) / 256;
    const int nscan = (n + 1023) / 1024;
    const int e4_grid = (E / 4 + 255) / 256;         // 4 edges per thread

    // lazily-created secondary stream + fork/join events (no device allocation;
    // identical launched work every call)
    static cudaStream_t s2 = nullptr;
    static cudaEvent_t evA = nullptr, evB = nullptr;
    if (s2 == nullptr) {
        cudaStreamCreateWithFlags(&s2, cudaStreamNonBlocking);
        cudaEventCreateWithFlags(&evA, cudaEventDisableTiming);
        cudaEventCreateWithFlags(&evB, cudaEventDisableTiming);
    }

    // ---- fork: branch B (fuse_heads + conv1 GEMM, independent of CSR) on s2 ----
    cudaEventRecord(evA, 0);
    cudaStreamWaitEvent(s2, evA, 0);
    fuse_heads_kernel<<<33, 256, 0, s2>>>(Wp1, bp1, Wp2, bp2, Wf, bf);
    mma_gemm_kernel<128, 0, false><<<GEMM_GRID, 256, SM128_FP, s2>>>(x, W1, nullptr, nullptr, nullptr, zb, n, ntiles);
    cudaEventRecord(evB, s2);

    // ---- branch A: CSR build on default stream (concurrent with branch B) ----
    zero_deg_kernel<<<(n + 255) / 256, 256>>>(deg, n);
    hist_kernel<<<e4_grid, 256>>>(dst, deg, E);
    scan_part_kernel <<<nscan, 256>>>(deg, bsum, n);
    scan_block_kernel<<<1, 128>>>(bsum, nscan);
    scan_final_kernel<<<nscan, 256>>>(deg, bsum, off, cur, dinv, n);
    bucket_kernel<<<e4_grid, 256>>>(src, dst, cur, srcs, E);

    // ---- join ----
    cudaStreamWaitEvent(0, evB, 0);

    // ---- conv1 aggregate (z unscaled: per-edge dinv[src]) ----
    aggregate_kernel<1, false><<<agg_grid, 256>>>((const uint2*)zb, off, srcs, dinv, b1, g1, be1, (uint2*)hb, n);

    // ---- conv2 (bf16 A; z scaled in GEMM epilogue) ----
    mma_gemm_kernel<128, 0, true><<<GEMM_GRID2, 256, SM128_BF>>>(hb, W2, nullptr, dinv, nullptr, zb, n, ntiles);
    aggregate_kernel<1, true><<<agg_grid, 256>>>((const uint2*)zb, off, srcs, dinv, b2, g2, be2, (uint2*)hb, n);

    // ---- conv3 (bf16 A, no LN; z scaled in GEMM epilogue) ----
    mma_gemm_kernel<128, 0, true><<<GEMM_GRID2, 256, SM128_BF>>>(hb, W3, nullptr, dinv, nullptr, zb, n, ntiles);
    aggregate_kernel<0, true><<<agg_grid, 256>>>((const uint2*)zb, off, srcs, dinv, b3, nullptr, nullptr, (uint2*)hb, n);

    // ---- fused head: out = sigmoid(h @ Wf + bf) (bf16 A) ----
    mma_gemm_kernel<64, 2, true><<<GEMM_GRID2, 256, SM64_BF>>>(hb, Wf, bf, nullptr, out, nullptr, n, ntiles);
}